// round 12
// baseline (speedup 1.0000x reference)
#include <cuda_runtime.h>
#include <cuda_fp16.h>
#include <cuda.h>
#include <cstdint>

#define B_   32
#define N_   1024
#define DIM_ 1152
#define H_   12
#define KV_  4
#define D_   96
#define MTOT (B_ * N_)        // 32768
#define KDIM 1152

// ---------------- scratch (device globals; no allocations) ----------------
__device__ float g_q[37748736];            // [B,N,1152] fp32 q
__device__ float g_kvp[25165824];          // [B,N,768] fp32 k|v
__device__ float g_kv[1179648];            // [B,KV,96,96]
__device__ float g_nq[768];                // (s2,s6) per (b,h)
__device__ float g_nk[256];                // (s2,s6) per (b,kv)
__device__ __align__(128) __half g_xh[37748736];   // A hi  (x, later pre-proj)
__device__ __align__(128) __half g_xm[37748736];   // A mid
__device__ __align__(128) __half g_wqh[1327104];   // wq^T  hi [1152][1152] K-major
__device__ __align__(128) __half g_wqm[1327104];
__device__ __align__(128) __half g_wkh[884736];    // wkv^T hi [768][1152]
__device__ __align__(128) __half g_wkm[884736];
__device__ __align__(128) __half g_wph[1327104];   // proj^T hi

// ---------------- PTX helpers ----------------
__device__ __forceinline__ void mma16(float* c, const uint32_t* a, const uint32_t* b) {
    asm volatile(
        "mma.sync.aligned.m16n8k16.row.col.f32.f16.f16.f32 "
        "{%0,%1,%2,%3},{%4,%5,%6,%7},{%8,%9},{%0,%1,%2,%3};"
        : "+f"(c[0]), "+f"(c[1]), "+f"(c[2]), "+f"(c[3])
        : "r"(a[0]), "r"(a[1]), "r"(a[2]), "r"(a[3]), "r"(b[0]), "r"(b[1]));
}
__device__ __forceinline__ void ldsm4(uint32_t* r, uint32_t addr) {
    asm volatile("ldmatrix.sync.aligned.m8n8.x4.shared.b16 {%0,%1,%2,%3}, [%4];"
        : "=r"(r[0]), "=r"(r[1]), "=r"(r[2]), "=r"(r[3]) : "r"(addr));
}
__device__ __forceinline__ void mbar_init(uint32_t a, uint32_t cnt) {
    asm volatile("mbarrier.init.shared.b64 [%0], %1;" :: "r"(a), "r"(cnt) : "memory");
}
__device__ __forceinline__ void mbar_expect(uint32_t a, uint32_t bytes) {
    asm volatile("mbarrier.arrive.expect_tx.shared.b64 _, [%0], %1;"
                 :: "r"(a), "r"(bytes) : "memory");
}
__device__ __forceinline__ void bar_wait(uint32_t a, uint32_t parity) {
    asm volatile(
        "{\n\t.reg .pred P;\n\t"
        "LAB_%=:\n\t"
        "mbarrier.try_wait.parity.acquire.cta.shared::cta.b64 P, [%0], %1, 0x989680;\n\t"
        "@!P bra LAB_%=;\n\t}"
        :: "r"(a), "r"(parity) : "memory");
}
__device__ __forceinline__ void tma2d(uint32_t dst, const void* map,
                                      int cx, int cy, uint32_t bar) {
    asm volatile(
        "cp.async.bulk.tensor.2d.shared::cta.global.tile.mbarrier::complete_tx::bytes "
        "[%0], [%1, {%2, %3}], [%4];"
        :: "r"(dst), "l"(map), "r"(cx), "r"(cy), "r"(bar) : "memory");
}

#define TILE 8192

// ==== split-fp16 GEMM via TMA + ldmatrix: 128x128 tile, 3-stage pipeline ==
// (R9-proven: CTA-wide syncthreads drain; direct __grid_constant__ refs)
// NT=3: C = Ah@Bh^T + Ah@Bm^T + Am@Bh^T (~fp32).  NT=1: C = Ah@Bh^T.
template<int NT>
__global__ __launch_bounds__(256, 2) void hgemm_tma(
    const __grid_constant__ CUtensorMap mAh,
    const __grid_constant__ CUtensorMap mAm,
    const __grid_constant__ CUtensorMap mBh,
    const __grid_constant__ CUtensorMap mBm,
    const float* __restrict__ bias, float* __restrict__ C, int Nout)
{
    extern __shared__ __align__(1024) char smem[];
    constexpr int NTILES = (NT == 3) ? 4 : 2;   // Ah[,Am],Bh[,Bm]
    constexpr int STAGE  = NTILES * TILE;
    constexpr int BHOFF  = ((NT == 3) ? 2 : 1) * TILE;
    const uint32_t sb = (uint32_t)__cvta_generic_to_shared(smem);
    const uint32_t bars = sb;                    // 3 mbarriers @ 0,8,16
    const uint32_t tiles_s = sb + 1024;

    const int tid  = threadIdx.x;
    const int lane = tid & 31, warp = tid >> 5;
    const int wm = warp >> 2, wn = warp & 3;     // 2 x 4 warps, 64x32 each
    const int gid = lane >> 2, tig = lane & 3;
    const int m8  = lane >> 3, low = lane & 7;   // ldmatrix lane decomposition
    const int arow = blockIdx.y * 128;
    const int brow = blockIdx.x * 128;

    // per-lane ldmatrix address invariants (SW64 swizzle)
    uint32_t aOff[4]; int aSw[4];
    #pragma unroll
    for (int ti = 0; ti < 4; ti++) {
        int r = wm * 64 + ti * 16 + ((m8 & 1) << 3) + low;
        aOff[ti] = (uint32_t)(r * 64);
        aSw[ti] = (r >> 1) & 3;
    }
    uint32_t bOff[2]; int bSw[2];
    #pragma unroll
    for (int p = 0; p < 2; p++) {
        int n = wn * 32 + p * 16 + ((m8 >> 1) << 3) + low;
        bOff[p] = (uint32_t)(n * 64);
        bSw[p] = (n >> 1) & 3;
    }
    const int cAm = m8 >> 1;   // chunk add for A matrices
    const int cBm = m8 & 1;    // chunk add for B matrices

    if (tid == 0) { mbar_init(bars, 1); mbar_init(bars + 8, 1); mbar_init(bars + 16, 1); }
    __syncthreads();

    auto issue = [&](int t, int b) {
        const uint32_t bar = bars + b * 8;
        const uint32_t st = tiles_s + b * STAGE;
        mbar_expect(bar, NTILES * TILE);
        const int k0 = t * 32;
        tma2d(st, &mAh, k0, arow, bar);
        if (NT == 3) {
            tma2d(st + TILE, &mAm, k0, arow, bar);
            tma2d(st + 2 * TILE, &mBh, k0, brow, bar);
            tma2d(st + 3 * TILE, &mBm, k0, brow, bar);
        } else {
            tma2d(st + TILE, &mBh, k0, brow, bar);
        }
    };

    float acc[4][4][4];
    #pragma unroll
    for (int i = 0; i < 4; i++)
        #pragma unroll
        for (int j = 0; j < 4; j++)
            #pragma unroll
            for (int r = 0; r < 4; r++) acc[i][j][r] = 0.f;

    const int T = KDIM / 32;                     // 36
    if (tid == 0) { issue(0, 0); issue(1, 1); issue(2, 2); }

    int buf = 0, ph = 0;
    for (int t = 0; t < T; t++) {
        bar_wait(bars + buf * 8, ph);
        const uint32_t st = tiles_s + buf * STAGE;

        #pragma unroll
        for (int ks = 0; ks < 2; ks++) {
            const int cB = ks * 2 + cBm;
            const int cA = ks * 2 + cAm;
            uint32_t bh[4][2], bm[4][2];
            ldsm4(&bh[0][0], st + BHOFF + bOff[0] + (uint32_t)((cB ^ bSw[0]) << 4));
            ldsm4(&bh[2][0], st + BHOFF + bOff[1] + (uint32_t)((cB ^ bSw[1]) << 4));
            if (NT == 3) {
                ldsm4(&bm[0][0], st + 3 * TILE + bOff[0] + (uint32_t)((cB ^ bSw[0]) << 4));
                ldsm4(&bm[2][0], st + 3 * TILE + bOff[1] + (uint32_t)((cB ^ bSw[1]) << 4));
            }
            #pragma unroll
            for (int ti = 0; ti < 4; ti++) {
                uint32_t ah[4], am[4];
                ldsm4(ah, st + aOff[ti] + (uint32_t)((cA ^ aSw[ti]) << 4));
                if (NT == 3)
                    ldsm4(am, st + TILE + aOff[ti] + (uint32_t)((cA ^ aSw[ti]) << 4));
                #pragma unroll
                for (int tj = 0; tj < 4; tj++) {
                    mma16(acc[ti][tj], ah, bh[tj]);
                    if (NT == 3) {
                        mma16(acc[ti][tj], ah, bm[tj]);
                        mma16(acc[ti][tj], am, bh[tj]);
                    }
                }
            }
        }
        __syncthreads();                          // all warps done with buf
        if (t + 3 < T && tid == 0) issue(t + 3, buf);
        buf++; if (buf == 3) { buf = 0; ph ^= 1; }
    }

    #pragma unroll
    for (int ti = 0; ti < 4; ti++) {
        #pragma unroll
        for (int tj = 0; tj < 4; tj++) {
            int row = arow + wm * 64 + ti * 16 + gid;
            int col = brow + wn * 32 + tj * 8 + tig * 2;
            float b0 = bias[col], b1 = bias[col + 1];
            float2 v0 = { acc[ti][tj][0] + b0, acc[ti][tj][1] + b1 };
            float2 v1 = { acc[ti][tj][2] + b0, acc[ti][tj][3] + b1 };
            *(float2*)(C + (size_t)row * Nout + col) = v0;
            *(float2*)(C + (size_t)(row + 8) * Nout + col) = v1;
        }
    }
}

// ---- split fp32 -> fp16 hi/mid ------------------------------------------
__global__ void split_kernel(const float* __restrict__ src,
                             __half* __restrict__ hi,
                             __half* __restrict__ mid, int n4)
{
    int i = blockIdx.x * blockDim.x + threadIdx.x;
    if (i >= n4) return;
    float4 v = ((const float4*)src)[i];
    __half h0 = __float2half(v.x), h1 = __float2half(v.y);
    __half h2 = __float2half(v.z), h3 = __float2half(v.w);
    __half2* hp = (__half2*)(hi + (size_t)i * 4);
    hp[0] = __half2(h0, h1);
    hp[1] = __half2(h2, h3);
    __half2* mp = (__half2*)(mid + (size_t)i * 4);
    mp[0] = __half2(__float2half(v.x - __half2float(h0)),
                    __float2half(v.y - __half2float(h1)));
    mp[1] = __half2(__float2half(v.z - __half2float(h2)),
                    __float2half(v.w - __half2float(h3)));
}

// ---- weight transpose + split: W[k][n] -> wT_hi/mid[n][k] ----------------
__global__ void wsplit_kernel(const float* __restrict__ W,
                              __half* __restrict__ hi,
                              __half* __restrict__ mid, int Nout)
{
    __shared__ float t[32][33];
    const int k0 = blockIdx.y * 32, nn0 = blockIdx.x * 32;
    const int tx = threadIdx.x, ty = threadIdx.y;
    for (int r = ty; r < 32; r += 8)
        t[r][tx] = W[(size_t)(k0 + r) * Nout + nn0 + tx];
    __syncthreads();
    for (int r = ty; r < 32; r += 8) {
        float v = t[tx][r];   // = W[k0+tx][nn0+r]
        __half h = __float2half(v);
        size_t o = (size_t)(nn0 + r) * KDIM + k0 + tx;
        hi[o] = h;
        if (mid) mid[o] = __float2half(v - __half2float(h));
    }
}

// ---- q focus norm partials ----------------------------------------------
__global__ void norm_kernel()
{
    const int bh = blockIdx.x;
    const int b = bh / H_, hh = bh - b * H_;
    const float* base = g_q + (size_t)b * N_ * DIM_ + hh * D_
                            + (size_t)blockIdx.y * 128 * DIM_;

    float s2 = 0.f, s6 = 0.f;
    int n = threadIdx.x / 96, d = threadIdx.x % 96;
    for (int i = threadIdx.x; i < 128 * 96; i += 256) {
        float v = fmaxf(base[(size_t)n * DIM_ + d], 0.f);
        float v2 = v * v, v3 = v2 * v;
        s2 += v2;
        s6 += v3 * v3;
        d += 64; n += 2;
        if (d >= 96) { d -= 96; n++; }
    }
    #pragma unroll
    for (int off = 16; off; off >>= 1) {
        s2 += __shfl_xor_sync(0xffffffffu, s2, off);
        s6 += __shfl_xor_sync(0xffffffffu, s6, off);
    }
    __shared__ float w2[8], w6[8];
    const int lane = threadIdx.x & 31, warp = threadIdx.x >> 5;
    if (lane == 0) { w2[warp] = s2; w6[warp] = s6; }
    __syncthreads();
    if (threadIdx.x == 0) {
        float t2 = 0.f, t6 = 0.f;
        #pragma unroll
        for (int i = 0; i < 8; i++) { t2 += w2[i]; t6 += w6[i]; }
        atomicAdd(&g_nq[bh * 2], t2);
        atomicAdd(&g_nq[bh * 2 + 1], t6);
    }
}

// ---- kv[d,e] += sum_n relu(k)^3 * v ; fused k-norm partials --------------
__global__ __launch_bounds__(256) void kv_gemm_kernel()
{
    const int b = blockIdx.x >> 2;
    const int g = blockIdx.x & 3;
    __shared__ float ks[32 * 96];
    __shared__ float vs[32 * 96];
    const int tid = threadIdx.x;
    const int ty = tid >> 4, tx = tid & 15;

    float acc[6][6];
    #pragma unroll
    for (int i = 0; i < 6; i++)
        #pragma unroll
        for (int j = 0; j < 6; j++) acc[i][j] = 0.f;

    float s2 = 0.f, s6 = 0.f;

    const float* kbase = g_kvp + (size_t)b * N_ * 768 + g * D_;
    const float* vbase = kbase + 384;
    const int t0b = blockIdx.y * 128;

    for (int t0 = t0b; t0 < t0b + 128; t0 += 32) {
        for (int i = tid; i < 32 * 96; i += 256) {
            int r = i / 96;
            int c = i - r * 96;
            size_t off = (size_t)(t0 + r) * 768 + c;
            float kl = fmaxf(kbase[off], 0.f);
            float k3 = kl * kl * kl;
            ks[i] = k3;
            vs[i] = vbase[off];
            s2 += kl * kl;
            s6 += k3 * k3;
        }
        __syncthreads();
        #pragma unroll 8
        for (int kk = 0; kk < 32; kk++) {
            float rk[6], rv[6];
            #pragma unroll
            for (int i = 0; i < 6; i++) rk[i] = ks[kk * 96 + ty * 6 + i];
            #pragma unroll
            for (int j = 0; j < 6; j++) rv[j] = vs[kk * 96 + tx * 6 + j];
            #pragma unroll
            for (int i = 0; i < 6; i++)
                #pragma unroll
                for (int j = 0; j < 6; j++)
                    acc[i][j] = fmaf(rk[i], rv[j], acc[i][j]);
        }
        __syncthreads();
    }
    float* dst = g_kv + (size_t)blockIdx.x * 96 * 96;
    #pragma unroll
    for (int i = 0; i < 6; i++)
        #pragma unroll
        for (int j = 0; j < 6; j++)
            atomicAdd(&dst[(ty * 6 + i) * 96 + tx * 6 + j], acc[i][j]);

    #pragma unroll
    for (int off = 16; off; off >>= 1) {
        s2 += __shfl_xor_sync(0xffffffffu, s2, off);
        s6 += __shfl_xor_sync(0xffffffffu, s6, off);
    }
    __shared__ float w2[8], w6[8];
    const int lane = tid & 31, warp = tid >> 5;
    if (lane == 0) { w2[warp] = s2; w6[warp] = s6; }
    __syncthreads();
    if (tid == 0) {
        float t2 = 0.f, t6 = 0.f;
        #pragma unroll
        for (int i = 0; i < 8; i++) { t2 += w2[i]; t6 += w6[i]; }
        atomicAdd(&g_nk[blockIdx.x * 2], t2);
        atomicAdd(&g_nk[blockIdx.x * 2 + 1], t6);
    }
}

// ---- attn + scale + fused 3x3 dwc; writes fp16 hi for proj ---------------
// dynamic smem: kvs[96*96] | qs[32*96] | vsm[3][34][96] | wsm[96*9] | bsm[96]
#define ATT_KVS 0
#define ATT_QS  36864
#define ATT_VSM 49152
#define ATT_WSM 88320
#define ATT_BSM 91776
#define ATT_SMEM 92160
__global__ __launch_bounds__(256) void attn_kernel(const float* __restrict__ dw,
                                                   const float* __restrict__ db)
{
    extern __shared__ __align__(16) char asm_[];
    float* kvs = (float*)(asm_ + ATT_KVS);
    float* qs  = (float*)(asm_ + ATT_QS);
    float (*vsm)[34][96] = (float (*)[34][96])(asm_ + ATT_VSM);
    float* wsm = (float*)(asm_ + ATT_WSM);
    float* bsm = (float*)(asm_ + ATT_BSM);

    const int bh = blockIdx.y;
    const int b = bh / H_;
    const int h = bh - b * H_;
    const int g = h & 3;
    const int y = blockIdx.x;            // latent row; n0 = y*32
    const int n0 = y * 32;
    const int tid = threadIdx.x;

    const float* kvsrc = g_kv + (size_t)(b * KV_ + g) * 9216;
    for (int i = tid; i < 9216; i += 256) kvs[i] = kvsrc[i];

    const float* qsrc = g_q + (size_t)(b * N_ + n0) * DIM_ + h * D_;
    for (int i = tid; i < 3072; i += 256) {
        int r = i / 96;
        int d = i - r * 96;
        float v = fmaxf(qsrc[(size_t)r * DIM_ + d], 0.f);
        qs[i] = v * v * v;
    }

    // dwc staging
    for (int i = tid; i < 864; i += 256) wsm[i] = dw[g * 96 * 9 + i];
    if (tid < 96) bsm[tid] = db[g * 96 + tid];
    for (int i = tid; i < 576; i += 256) {
        int dy = i / 192, rem = i - dy * 192;
        int side = rem / 96, c = rem - side * 96;
        vsm[dy][side ? 33 : 0][c] = 0.f;
    }
    const float* vsrc = g_kvp + (size_t)b * N_ * 768 + 384 + g * 96;
    for (int i = tid; i < 9216; i += 256) {
        int dy = i / 3072, rem = i - dy * 3072;
        int xx = rem / 96, c = rem - xx * 96;
        int yy = y + dy - 1;
        float v = 0.f;
        if (yy >= 0 && yy < 32)
            v = vsrc[(size_t)(yy * 32 + xx) * 768 + c];
        vsm[dy][xx + 1][c] = v;
    }
    __syncthreads();

    const int ty = tid >> 4, tx = tid & 15;
    float acc[2][6];
    #pragma unroll
    for (int i = 0; i < 2; i++)
        #pragma unroll
        for (int j = 0; j < 6; j++) acc[i][j] = 0.f;

    #pragma unroll 4
    for (int k = 0; k < 96; k++) {
        float q0 = qs[(ty * 2 + 0) * 96 + k];
        float q1 = qs[(ty * 2 + 1) * 96 + k];
        float rv[6];
        #pragma unroll
        for (int j = 0; j < 6; j++) rv[j] = kvs[k * 96 + tx * 6 + j];
        #pragma unroll
        for (int j = 0; j < 6; j++) {
            acc[0][j] = fmaf(q0, rv[j], acc[0][j]);
            acc[1][j] = fmaf(q1, rv[j], acc[1][j]);
        }
    }

    const float s2q = g_nq[bh * 2],            s6q = g_nq[bh * 2 + 1];
    const float s2k = g_nk[(b * KV_ + g) * 2], s6k = g_nk[(b * KV_ + g) * 2 + 1];
    const float den = s6q * s6k;
    const float scale = (den > 0.f) ? sqrtf((s2q * s2k) / den) : 0.f;

    #pragma unroll
    for (int i = 0; i < 2; i++) {
        int r = ty * 2 + i;                       // x position on latent row
        size_t rowbase = (size_t)(b * N_ + n0 + r) * DIM_ + h * D_;
        #pragma unroll
        for (int j = 0; j < 6; j++) {
            int e = tx * 6 + j;
            float o = bsm[e];
            const float* w = wsm + e * 9;
            #pragma unroll
            for (int dy = 0; dy < 3; dy++)
                #pragma unroll
                for (int dx = 0; dx < 3; dx++)
                    o = fmaf(w[dy * 3 + dx], vsm[dy][r + dx][e], o);
            float val = fmaf(acc[i][j], scale, o);
            g_xh[rowbase + e] = __float2half(val);
        }
    }
}

// ---------------- host: tensor-map construction ----------------
typedef CUresult (*PFN_tmap)(
    CUtensorMap*, CUtensorMapDataType, cuuint32_t, void*,
    const cuuint64_t*, const cuuint64_t*, const cuuint32_t*, const cuuint32_t*,
    CUtensorMapInterleave, CUtensorMapSwizzle, CUtensorMapL2promotion,
    CUtensorMapFloatOOBfill);

static void make_map(PFN_tmap fn, CUtensorMap* m, void* ptr, uint64_t rows)
{
    cuuint64_t dims[2]    = { (cuuint64_t)KDIM, (cuuint64_t)rows };
    cuuint64_t strides[1] = { (cuuint64_t)KDIM * 2 };
    cuuint32_t box[2]     = { 32, 128 };
    cuuint32_t es[2]      = { 1, 1 };
    fn(m, CU_TENSOR_MAP_DATA_TYPE_FLOAT16, 2, ptr, dims, strides, box, es,
       CU_TENSOR_MAP_INTERLEAVE_NONE, CU_TENSOR_MAP_SWIZZLE_64B,
       CU_TENSOR_MAP_L2_PROMOTION_L2_128B, CU_TENSOR_MAP_FLOAT_OOB_FILL_NONE);
}

// ---------------- launch ----------------
extern "C" void kernel_launch(void* const* d_in, const int* in_sizes, int n_in,
                              void* d_out, int out_size)
{
    const float* x      = (const float*)d_in[0];
    const float* wq_w   = (const float*)d_in[1];
    const float* wq_b   = (const float*)d_in[2];
    const float* wkv_w  = (const float*)d_in[3];
    const float* wkv_b  = (const float*)d_in[4];
    const float* dwc_w  = (const float*)d_in[5];
    const float* dwc_b  = (const float*)d_in[6];
    const float* proj_w = (const float*)d_in[7];
    const float* proj_b = (const float*)d_in[8];
    float* out = (float*)d_out;

    cudaFuncSetAttribute(hgemm_tma<3>, cudaFuncAttributeMaxDynamicSharedMemorySize, 99328);
    cudaFuncSetAttribute(hgemm_tma<1>, cudaFuncAttributeMaxDynamicSharedMemorySize, 50176);
    cudaFuncSetAttribute(attn_kernel, cudaFuncAttributeMaxDynamicSharedMemorySize, ATT_SMEM);

    float *gq, *gkvp, *gnq, *gnk, *gkv;
    __half *xh, *xm, *wqh, *wqm, *wkh, *wkm, *wph;
    cudaGetSymbolAddress((void**)&gq,   g_q);
    cudaGetSymbolAddress((void**)&gkvp, g_kvp);
    cudaGetSymbolAddress((void**)&gnq,  g_nq);
    cudaGetSymbolAddress((void**)&gnk,  g_nk);
    cudaGetSymbolAddress((void**)&gkv,  g_kv);
    cudaGetSymbolAddress((void**)&xh,   g_xh);
    cudaGetSymbolAddress((void**)&xm,   g_xm);
    cudaGetSymbolAddress((void**)&wqh,  g_wqh);
    cudaGetSymbolAddress((void**)&wqm,  g_wqm);
    cudaGetSymbolAddress((void**)&wkh,  g_wkh);
    cudaGetSymbolAddress((void**)&wkm,  g_wkm);
    cudaGetSymbolAddress((void**)&wph,  g_wph);

    static PFN_tmap fn = nullptr;
    if (!fn) {
        cudaDriverEntryPointQueryResult qr;
        cudaGetDriverEntryPoint("cuTensorMapEncodeTiled", (void**)&fn,
                                cudaEnableDefault, &qr);
    }
    CUtensorMap mXh, mXm, mWqh, mWqm, mWkh, mWkm, mWph;
    make_map(fn, &mXh,  xh,  MTOT);
    make_map(fn, &mXm,  xm,  MTOT);
    make_map(fn, &mWqh, wqh, DIM_);
    make_map(fn, &mWqm, wqm, DIM_);
    make_map(fn, &mWkh, wkh, 768);
    make_map(fn, &mWkm, wkm, 768);
    make_map(fn, &mWph, wph, DIM_);

    cudaMemsetAsync(gnq, 0, 768 * sizeof(float));
    cudaMemsetAsync(gnk, 0, 256 * sizeof(float));
    cudaMemsetAsync(gkv, 0, 1179648 * sizeof(float));

    // prep: splits + weight transposes
    split_kernel<<<(MTOT * DIM_ / 4 + 255) / 256, 256>>>(x, xh, xm, MTOT * DIM_ / 4);
    wsplit_kernel<<<dim3(DIM_ / 32, KDIM / 32), dim3(32, 8)>>>(wq_w, wqh, wqm, DIM_);
    wsplit_kernel<<<dim3(768  / 32, KDIM / 32), dim3(32, 8)>>>(wkv_w, wkh, wkm, 768);
    wsplit_kernel<<<dim3(DIM_ / 32, KDIM / 32), dim3(32, 8)>>>(proj_w, wph, nullptr, DIM_);

    // q and kv projections: 3-term split-fp16 (~fp32 accurate)
    hgemm_tma<3><<<dim3(DIM_ / 128, MTOT / 128), 256, 99328>>>(
        mXh, mXm, mWqh, mWqm, wq_b, gq, DIM_);
    hgemm_tma<3><<<dim3(768 / 128, MTOT / 128), 256, 99328>>>(
        mXh, mXm, mWkh, mWkm, wkv_b, gkvp, 768);

    norm_kernel<<<dim3(B_ * H_, 8), 256>>>();
    kv_gemm_kernel<<<dim3(B_ * KV_, 8), 256>>>();    // + fused k-norm
    attn_kernel<<<dim3(32, B_ * H_), 256, ATT_SMEM>>>(dwc_w, dwc_b);  // + fused dwc

    // out projection: 1-term fp16 (error not cube-amplified)
    hgemm_tma<1><<<dim3(DIM_ / 128, MTOT / 128), 256, 50176>>>(
        mXh, mXm, mWph, mWph, proj_b, out, DIM_);
}

// round 13
// speedup vs baseline: 1.2232x; 1.2232x over previous
#include <cuda_runtime.h>
#include <cuda_fp16.h>
#include <cuda.h>
#include <cstdint>

#define B_   32
#define N_   1024
#define DIM_ 1152
#define H_   12
#define KV_  4
#define D_   96
#define MTOT (B_ * N_)        // 32768
#define KDIM 1152

// ---------------- scratch (device globals; no allocations) ----------------
__device__ float g_q[37748736];            // [B,N,1152] fp32 q
__device__ float g_kvp[25165824];          // [B,N,768] fp32 k|v
__device__ float g_dwc[12582912];          // [B,N,384]
__device__ float g_kv[1179648];            // [B,KV,96,96]
__device__ float g_nq[768];                // (s2,s6) per (b,h)
__device__ float g_nk[256];                // (s2,s6) per (b,kv)
__device__ __align__(128) __half g_xh[37748736];   // A hi  (x, later pre-proj)
__device__ __align__(128) __half g_xm[37748736];   // A mid
__device__ __align__(128) __half g_wqh[1327104];   // wq^T  hi [1152][1152] K-major
__device__ __align__(128) __half g_wqm[1327104];
__device__ __align__(128) __half g_wkh[884736];    // wkv^T hi [768][1152]
__device__ __align__(128) __half g_wkm[884736];
__device__ __align__(128) __half g_wph[1327104];   // proj^T hi

// ---------------- PTX helpers ----------------
__device__ __forceinline__ void mma16(float* c, const uint32_t* a, const uint32_t* b) {
    asm volatile(
        "mma.sync.aligned.m16n8k16.row.col.f32.f16.f16.f32 "
        "{%0,%1,%2,%3},{%4,%5,%6,%7},{%8,%9},{%0,%1,%2,%3};"
        : "+f"(c[0]), "+f"(c[1]), "+f"(c[2]), "+f"(c[3])
        : "r"(a[0]), "r"(a[1]), "r"(a[2]), "r"(a[3]), "r"(b[0]), "r"(b[1]));
}
__device__ __forceinline__ void ldsm4(uint32_t* r, uint32_t addr) {
    asm volatile("ldmatrix.sync.aligned.m8n8.x4.shared.b16 {%0,%1,%2,%3}, [%4];"
        : "=r"(r[0]), "=r"(r[1]), "=r"(r[2]), "=r"(r[3]) : "r"(addr));
}
__device__ __forceinline__ void mbar_init(uint32_t a, uint32_t cnt) {
    asm volatile("mbarrier.init.shared.b64 [%0], %1;" :: "r"(a), "r"(cnt) : "memory");
}
__device__ __forceinline__ void mbar_expect(uint32_t a, uint32_t bytes) {
    asm volatile("mbarrier.arrive.expect_tx.shared.b64 _, [%0], %1;"
                 :: "r"(a), "r"(bytes) : "memory");
}
__device__ __forceinline__ void bar_wait(uint32_t a, uint32_t parity) {
    asm volatile(
        "{\n\t.reg .pred P;\n\t"
        "LAB_%=:\n\t"
        "mbarrier.try_wait.parity.acquire.cta.shared::cta.b64 P, [%0], %1, 0x989680;\n\t"
        "@!P bra LAB_%=;\n\t}"
        :: "r"(a), "r"(parity) : "memory");
}
__device__ __forceinline__ void tma2d(uint32_t dst, const void* map,
                                      int cx, int cy, uint32_t bar) {
    asm volatile(
        "cp.async.bulk.tensor.2d.shared::cta.global.tile.mbarrier::complete_tx::bytes "
        "[%0], [%1, {%2, %3}], [%4];"
        :: "r"(dst), "l"(map), "r"(cx), "r"(cy), "r"(bar) : "memory");
}

#define TILE 8192

// ==== split-fp16 GEMM via TMA + ldmatrix: 128x128 tile, 3-stage pipeline ==
// (R9-proven pipeline.)  NT=3: 3-term (~fp32).  NT=1: hi-only.
// qnrm != nullptr (q-proj only): fused focus-norm partials (s2,s6) per (b,h).
template<int NT>
__global__ __launch_bounds__(256, 2) void hgemm_tma(
    const __grid_constant__ CUtensorMap mAh,
    const __grid_constant__ CUtensorMap mAm,
    const __grid_constant__ CUtensorMap mBh,
    const __grid_constant__ CUtensorMap mBm,
    const float* __restrict__ bias, float* __restrict__ C, int Nout,
    float* qnrm)
{
    extern __shared__ __align__(1024) char smem[];
    constexpr int NTILES = (NT == 3) ? 4 : 2;   // Ah[,Am],Bh[,Bm]
    constexpr int STAGE  = NTILES * TILE;
    constexpr int BHOFF  = ((NT == 3) ? 2 : 1) * TILE;
    const uint32_t sb = (uint32_t)__cvta_generic_to_shared(smem);
    const uint32_t bars = sb;                    // 3 mbarriers @ 0,8,16
    const uint32_t tiles_s = sb + 1024;
    float* nbins = (float*)(smem + 64);          // 4 floats, header scratch

    const int tid  = threadIdx.x;
    const int lane = tid & 31, warp = tid >> 5;
    const int wm = warp >> 2, wn = warp & 3;     // 2 x 4 warps, 64x32 each
    const int gid = lane >> 2, tig = lane & 3;
    const int m8  = lane >> 3, low = lane & 7;   // ldmatrix lane decomposition
    const int arow = blockIdx.y * 128;
    const int brow = blockIdx.x * 128;

    // per-lane ldmatrix address invariants (SW64 swizzle)
    uint32_t aOff[4]; int aSw[4];
    #pragma unroll
    for (int ti = 0; ti < 4; ti++) {
        int r = wm * 64 + ti * 16 + ((m8 & 1) << 3) + low;
        aOff[ti] = (uint32_t)(r * 64);
        aSw[ti] = (r >> 1) & 3;
    }
    uint32_t bOff[2]; int bSw[2];
    #pragma unroll
    for (int p = 0; p < 2; p++) {
        int n = wn * 32 + p * 16 + ((m8 >> 1) << 3) + low;
        bOff[p] = (uint32_t)(n * 64);
        bSw[p] = (n >> 1) & 3;
    }
    const int cAm = m8 >> 1;   // chunk add for A matrices
    const int cBm = m8 & 1;    // chunk add for B matrices

    if (tid == 0) { mbar_init(bars, 1); mbar_init(bars + 8, 1); mbar_init(bars + 16, 1); }
    __syncthreads();

    auto issue = [&](int t, int b) {
        const uint32_t bar = bars + b * 8;
        const uint32_t st = tiles_s + b * STAGE;
        mbar_expect(bar, NTILES * TILE);
        const int k0 = t * 32;
        tma2d(st, &mAh, k0, arow, bar);
        if (NT == 3) {
            tma2d(st + TILE, &mAm, k0, arow, bar);
            tma2d(st + 2 * TILE, &mBh, k0, brow, bar);
            tma2d(st + 3 * TILE, &mBm, k0, brow, bar);
        } else {
            tma2d(st + TILE, &mBh, k0, brow, bar);
        }
    };

    float acc[4][4][4];
    #pragma unroll
    for (int i = 0; i < 4; i++)
        #pragma unroll
        for (int j = 0; j < 4; j++)
            #pragma unroll
            for (int r = 0; r < 4; r++) acc[i][j][r] = 0.f;

    const int T = KDIM / 32;                     // 36
    if (tid == 0) { issue(0, 0); issue(1, 1); issue(2, 2); }

    int buf = 0, ph = 0;
    for (int t = 0; t < T; t++) {
        bar_wait(bars + buf * 8, ph);
        const uint32_t st = tiles_s + buf * STAGE;

        #pragma unroll
        for (int ks = 0; ks < 2; ks++) {
            const int cB = ks * 2 + cBm;
            const int cA = ks * 2 + cAm;
            uint32_t bh[4][2], bm[4][2];
            ldsm4(&bh[0][0], st + BHOFF + bOff[0] + (uint32_t)((cB ^ bSw[0]) << 4));
            ldsm4(&bh[2][0], st + BHOFF + bOff[1] + (uint32_t)((cB ^ bSw[1]) << 4));
            if (NT == 3) {
                ldsm4(&bm[0][0], st + 3 * TILE + bOff[0] + (uint32_t)((cB ^ bSw[0]) << 4));
                ldsm4(&bm[2][0], st + 3 * TILE + bOff[1] + (uint32_t)((cB ^ bSw[1]) << 4));
            }
            #pragma unroll
            for (int ti = 0; ti < 4; ti++) {
                uint32_t ah[4], am[4];
                ldsm4(ah, st + aOff[ti] + (uint32_t)((cA ^ aSw[ti]) << 4));
                if (NT == 3)
                    ldsm4(am, st + TILE + aOff[ti] + (uint32_t)((cA ^ aSw[ti]) << 4));
                #pragma unroll
                for (int tj = 0; tj < 4; tj++) {
                    mma16(acc[ti][tj], ah, bh[tj]);
                    if (NT == 3) {
                        mma16(acc[ti][tj], ah, bm[tj]);
                        mma16(acc[ti][tj], am, bh[tj]);
                    }
                }
            }
        }
        __syncthreads();                          // all warps done with buf
        if (t + 3 < T && tid == 0) issue(t + 3, buf);
        buf++; if (buf == 3) { buf = 0; ph ^= 1; }
    }

    float s2l[2] = {0.f, 0.f}, s6l[2] = {0.f, 0.f};
    const int h0 = brow / 96;

    #pragma unroll
    for (int ti = 0; ti < 4; ti++) {
        #pragma unroll
        for (int tj = 0; tj < 4; tj++) {
            int row = arow + wm * 64 + ti * 16 + gid;
            int col = brow + wn * 32 + tj * 8 + tig * 2;
            float b0 = bias[col], b1 = bias[col + 1];
            float2 v0 = { acc[ti][tj][0] + b0, acc[ti][tj][1] + b1 };
            float2 v1 = { acc[ti][tj][2] + b0, acc[ti][tj][3] + b1 };
            *(float2*)(C + (size_t)row * Nout + col) = v0;
            *(float2*)(C + (size_t)(row + 8) * Nout + col) = v1;
            if (NT == 3 && qnrm) {
                int hb = col / 96 - h0;           // 0 or 1 (pair shares head)
                float r0 = fmaxf(v0.x, 0.f), r1 = fmaxf(v0.y, 0.f);
                float r2 = fmaxf(v1.x, 0.f), r3 = fmaxf(v1.y, 0.f);
                float q2 = r0 * r0 + r1 * r1 + r2 * r2 + r3 * r3;
                float c0 = r0 * r0 * r0, c1 = r1 * r1 * r1;
                float c2 = r2 * r2 * r2, c3 = r3 * r3 * r3;
                float q6 = c0 * c0 + c1 * c1 + c2 * c2 + c3 * c3;
                s2l[hb] += q2;
                s6l[hb] += q6;
            }
        }
    }

    if (NT == 3 && qnrm) {
        if (tid < 4) nbins[tid] = 0.f;
        __syncthreads();
        atomicAdd(&nbins[0], s2l[0]);
        atomicAdd(&nbins[1], s6l[0]);
        atomicAdd(&nbins[2], s2l[1]);
        atomicAdd(&nbins[3], s6l[1]);
        __syncthreads();
        if (tid < 4) {
            int head = h0 + (tid >> 1);
            int b = blockIdx.y >> 3;              // arow/1024
            atomicAdd(&qnrm[(b * H_ + head) * 2 + (tid & 1)], nbins[tid]);
        }
    }
}

// ---- split fp32 -> fp16 hi/mid ------------------------------------------
__global__ void split_kernel(const float* __restrict__ src,
                             __half* __restrict__ hi,
                             __half* __restrict__ mid, int n4)
{
    int i = blockIdx.x * blockDim.x + threadIdx.x;
    if (i >= n4) return;
    float4 v = ((const float4*)src)[i];
    __half h0 = __float2half(v.x), h1 = __float2half(v.y);
    __half h2 = __float2half(v.z), h3 = __float2half(v.w);
    __half2* hp = (__half2*)(hi + (size_t)i * 4);
    hp[0] = __half2(h0, h1);
    hp[1] = __half2(h2, h3);
    __half2* mp = (__half2*)(mid + (size_t)i * 4);
    mp[0] = __half2(__float2half(v.x - __half2float(h0)),
                    __float2half(v.y - __half2float(h1)));
    mp[1] = __half2(__float2half(v.z - __half2float(h2)),
                    __float2half(v.w - __half2float(h3)));
}

// ---- weight transpose + split: W[k][n] -> wT_hi/mid[n][k] ----------------
__global__ void wsplit_kernel(const float* __restrict__ W,
                              __half* __restrict__ hi,
                              __half* __restrict__ mid, int Nout)
{
    __shared__ float t[32][33];
    const int k0 = blockIdx.y * 32, nn0 = blockIdx.x * 32;
    const int tx = threadIdx.x, ty = threadIdx.y;
    for (int r = ty; r < 32; r += 8)
        t[r][tx] = W[(size_t)(k0 + r) * Nout + nn0 + tx];
    __syncthreads();
    for (int r = ty; r < 32; r += 8) {
        float v = t[tx][r];   // = W[k0+tx][nn0+r]
        __half h = __float2half(v);
        size_t o = (size_t)(nn0 + r) * KDIM + k0 + tx;
        hi[o] = h;
        if (mid) mid[o] = __float2half(v - __half2float(h));
    }
}

// ---- kv[d,e] += sum_n relu(k)^3 * v ; fused k-norm partials --------------
__global__ __launch_bounds__(256) void kv_gemm_kernel()
{
    const int b = blockIdx.x >> 2;
    const int g = blockIdx.x & 3;
    __shared__ float ks[32 * 96];
    __shared__ float vs[32 * 96];
    const int tid = threadIdx.x;
    const int ty = tid >> 4, tx = tid & 15;

    float acc[6][6];
    #pragma unroll
    for (int i = 0; i < 6; i++)
        #pragma unroll
        for (int j = 0; j < 6; j++) acc[i][j] = 0.f;

    float s2 = 0.f, s6 = 0.f;

    const float* kbase = g_kvp + (size_t)b * N_ * 768 + g * D_;
    const float* vbase = kbase + 384;
    const int t0b = blockIdx.y * 128;

    for (int t0 = t0b; t0 < t0b + 128; t0 += 32) {
        for (int i = tid; i < 32 * 96; i += 256) {
            int r = i / 96;
            int c = i - r * 96;
            size_t off = (size_t)(t0 + r) * 768 + c;
            float kl = fmaxf(kbase[off], 0.f);
            float k3 = kl * kl * kl;
            ks[i] = k3;
            vs[i] = vbase[off];
            s2 += kl * kl;
            s6 += k3 * k3;
        }
        __syncthreads();
        #pragma unroll 8
        for (int kk = 0; kk < 32; kk++) {
            float rk[6], rv[6];
            #pragma unroll
            for (int i = 0; i < 6; i++) rk[i] = ks[kk * 96 + ty * 6 + i];
            #pragma unroll
            for (int j = 0; j < 6; j++) rv[j] = vs[kk * 96 + tx * 6 + j];
            #pragma unroll
            for (int i = 0; i < 6; i++)
                #pragma unroll
                for (int j = 0; j < 6; j++)
                    acc[i][j] = fmaf(rk[i], rv[j], acc[i][j]);
        }
        __syncthreads();
    }
    float* dst = g_kv + (size_t)blockIdx.x * 96 * 96;
    #pragma unroll
    for (int i = 0; i < 6; i++)
        #pragma unroll
        for (int j = 0; j < 6; j++)
            atomicAdd(&dst[(ty * 6 + i) * 96 + tx * 6 + j], acc[i][j]);

    #pragma unroll
    for (int off = 16; off; off >>= 1) {
        s2 += __shfl_xor_sync(0xffffffffu, s2, off);
        s6 += __shfl_xor_sync(0xffffffffu, s6, off);
    }
    __shared__ float w2[8], w6[8];
    const int lane = tid & 31, warp = tid >> 5;
    if (lane == 0) { w2[warp] = s2; w6[warp] = s6; }
    __syncthreads();
    if (tid == 0) {
        float t2 = 0.f, t6 = 0.f;
        #pragma unroll
        for (int i = 0; i < 8; i++) { t2 += w2[i]; t6 += w6[i]; }
        atomicAdd(&g_nk[blockIdx.x * 2], t2);
        atomicAdd(&g_nk[blockIdx.x * 2 + 1], t6);
    }
}

// ---- depthwise 3x3 conv --------------------------------------------------
__global__ __launch_bounds__(384) void dwc_kernel(const float* __restrict__ w,
                                                  const float* __restrict__ bia)
{
    const int y = blockIdx.x;
    const int b = blockIdx.y;
    const int c = threadIdx.x;

    float wr[9];
    #pragma unroll
    for (int i = 0; i < 9; i++) wr[i] = w[c * 9 + i];
    const float bv = bia[c];

    const float* base = g_kvp + (size_t)b * N_ * 768 + 384 + c;
    const float* r0 = base + (size_t)(y * 32) * 768;
    const float* rm = r0 - (size_t)32 * 768;
    const float* rp = r0 + (size_t)32 * 768;
    const bool vm = (y > 0), vp = (y < 31);

    float A0 = 0.f, A1 = 0.f, A2 = 0.f;
    float Bc0, Bc1, Bc2, Cc0, Cc1, Cc2;
    Bc0 = vm ? rm[0] : 0.f;
    Bc1 = r0[0];
    Bc2 = vp ? rp[0] : 0.f;

    float* out = g_dwc + (size_t)(b * N_ + y * 32) * 384 + c;
    for (int x = 0; x < 32; x++) {
        if (x < 31) {
            size_t o = (size_t)(x + 1) * 768;
            Cc0 = vm ? rm[o] : 0.f;
            Cc1 = r0[o];
            Cc2 = vp ? rp[o] : 0.f;
        } else {
            Cc0 = Cc1 = Cc2 = 0.f;
        }
        float o = bv;
        o = fmaf(A0, wr[0], o); o = fmaf(Bc0, wr[1], o); o = fmaf(Cc0, wr[2], o);
        o = fmaf(A1, wr[3], o); o = fmaf(Bc1, wr[4], o); o = fmaf(Cc1, wr[5], o);
        o = fmaf(A2, wr[6], o); o = fmaf(Bc2, wr[7], o); o = fmaf(Cc2, wr[8], o);
        out[(size_t)x * 384] = o;
        A0 = Bc0; A1 = Bc1; A2 = Bc2;
        Bc0 = Cc0; Bc1 = Cc1; Bc2 = Cc2;
    }
}

// ---- attn + scale + dwc add; kv tile reused across 4 q-chunks ------------
__global__ __launch_bounds__(256) void attn_kernel()
{
    __shared__ float kvs[96 * 96];
    __shared__ float qs[32 * 96];
    const int bh = blockIdx.y;
    const int b = bh / H_;
    const int h = bh - b * H_;
    const int g = h & 3;
    const int nbase = blockIdx.x * 128;
    const int tid = threadIdx.x;

    const float* kvsrc = g_kv + (size_t)(b * KV_ + g) * 9216;
    for (int i = tid; i < 9216; i += 256) kvs[i] = kvsrc[i];

    const float s2q = g_nq[bh * 2],            s6q = g_nq[bh * 2 + 1];
    const float s2k = g_nk[(b * KV_ + g) * 2], s6k = g_nk[(b * KV_ + g) * 2 + 1];
    const float den = s6q * s6k;
    const float scale = (den > 0.f) ? sqrtf((s2q * s2k) / den) : 0.f;

    const int ty = tid >> 4, tx = tid & 15;

    for (int c4 = 0; c4 < 4; c4++) {
        const int n0 = nbase + c4 * 32;
        const float* qsrc = g_q + (size_t)(b * N_ + n0) * DIM_ + h * D_;
        for (int i = tid; i < 3072; i += 256) {
            int r = i / 96;
            int d = i - r * 96;
            float v = fmaxf(qsrc[(size_t)r * DIM_ + d], 0.f);
            qs[i] = v * v * v;
        }
        __syncthreads();

        float acc[2][6];
        #pragma unroll
        for (int i = 0; i < 2; i++)
            #pragma unroll
            for (int j = 0; j < 6; j++) acc[i][j] = 0.f;

        #pragma unroll 4
        for (int k = 0; k < 96; k++) {
            float q0 = qs[(ty * 2 + 0) * 96 + k];
            float q1 = qs[(ty * 2 + 1) * 96 + k];
            float rv[6];
            #pragma unroll
            for (int j = 0; j < 6; j++) rv[j] = kvs[k * 96 + tx * 6 + j];
            #pragma unroll
            for (int j = 0; j < 6; j++) {
                acc[0][j] = fmaf(q0, rv[j], acc[0][j]);
                acc[1][j] = fmaf(q1, rv[j], acc[1][j]);
            }
        }

        const float* dsrc = g_dwc + (size_t)(b * N_ + n0) * 384 + g * D_;
        #pragma unroll
        for (int i = 0; i < 2; i++) {
            int r = ty * 2 + i;
            size_t rowbase = (size_t)(b * N_ + n0 + r) * DIM_ + h * D_;
            #pragma unroll
            for (int j = 0; j < 6; j++) {
                int e = tx * 6 + j;
                float val = acc[i][j] * scale + dsrc[(size_t)r * 384 + e];
                g_xh[rowbase + e] = __float2half(val);
            }
        }
        __syncthreads();   // qs reused next chunk
    }
}

// ---------------- host: tensor-map construction ----------------
typedef CUresult (*PFN_tmap)(
    CUtensorMap*, CUtensorMapDataType, cuuint32_t, void*,
    const cuuint64_t*, const cuuint64_t*, const cuuint32_t*, const cuuint32_t*,
    CUtensorMapInterleave, CUtensorMapSwizzle, CUtensorMapL2promotion,
    CUtensorMapFloatOOBfill);

static void make_map(PFN_tmap fn, CUtensorMap* m, void* ptr, uint64_t rows)
{
    cuuint64_t dims[2]    = { (cuuint64_t)KDIM, (cuuint64_t)rows };
    cuuint64_t strides[1] = { (cuuint64_t)KDIM * 2 };
    cuuint32_t box[2]     = { 32, 128 };
    cuuint32_t es[2]      = { 1, 1 };
    fn(m, CU_TENSOR_MAP_DATA_TYPE_FLOAT16, 2, ptr, dims, strides, box, es,
       CU_TENSOR_MAP_INTERLEAVE_NONE, CU_TENSOR_MAP_SWIZZLE_64B,
       CU_TENSOR_MAP_L2_PROMOTION_L2_128B, CU_TENSOR_MAP_FLOAT_OOB_FILL_NONE);
}

// ---------------- launch ----------------
extern "C" void kernel_launch(void* const* d_in, const int* in_sizes, int n_in,
                              void* d_out, int out_size)
{
    const float* x      = (const float*)d_in[0];
    const float* wq_w   = (const float*)d_in[1];
    const float* wq_b   = (const float*)d_in[2];
    const float* wkv_w  = (const float*)d_in[3];
    const float* wkv_b  = (const float*)d_in[4];
    const float* dwc_w  = (const float*)d_in[5];
    const float* dwc_b  = (const float*)d_in[6];
    const float* proj_w = (const float*)d_in[7];
    const float* proj_b = (const float*)d_in[8];
    float* out = (float*)d_out;

    cudaFuncSetAttribute(hgemm_tma<3>, cudaFuncAttributeMaxDynamicSharedMemorySize, 99328);
    cudaFuncSetAttribute(hgemm_tma<1>, cudaFuncAttributeMaxDynamicSharedMemorySize, 50176);

    float *gq, *gkvp, *gnq, *gnk, *gkv;
    __half *xh, *xm, *wqh, *wqm, *wkh, *wkm, *wph;
    cudaGetSymbolAddress((void**)&gq,   g_q);
    cudaGetSymbolAddress((void**)&gkvp, g_kvp);
    cudaGetSymbolAddress((void**)&gnq,  g_nq);
    cudaGetSymbolAddress((void**)&gnk,  g_nk);
    cudaGetSymbolAddress((void**)&gkv,  g_kv);
    cudaGetSymbolAddress((void**)&xh,   g_xh);
    cudaGetSymbolAddress((void**)&xm,   g_xm);
    cudaGetSymbolAddress((void**)&wqh,  g_wqh);
    cudaGetSymbolAddress((void**)&wqm,  g_wqm);
    cudaGetSymbolAddress((void**)&wkh,  g_wkh);
    cudaGetSymbolAddress((void**)&wkm,  g_wkm);
    cudaGetSymbolAddress((void**)&wph,  g_wph);

    static PFN_tmap fn = nullptr;
    if (!fn) {
        cudaDriverEntryPointQueryResult qr;
        cudaGetDriverEntryPoint("cuTensorMapEncodeTiled", (void**)&fn,
                                cudaEnableDefault, &qr);
    }
    CUtensorMap mXh, mXm, mWqh, mWqm, mWkh, mWkm, mWph;
    make_map(fn, &mXh,  xh,  MTOT);
    make_map(fn, &mXm,  xm,  MTOT);
    make_map(fn, &mWqh, wqh, DIM_);
    make_map(fn, &mWqm, wqm, DIM_);
    make_map(fn, &mWkh, wkh, 768);
    make_map(fn, &mWkm, wkm, 768);
    make_map(fn, &mWph, wph, DIM_);

    cudaMemsetAsync(gnq, 0, 768 * sizeof(float));
    cudaMemsetAsync(gnk, 0, 256 * sizeof(float));
    cudaMemsetAsync(gkv, 0, 1179648 * sizeof(float));

    // prep: splits + weight transposes
    split_kernel<<<(MTOT * DIM_ / 4 + 255) / 256, 256>>>(x, xh, xm, MTOT * DIM_ / 4);
    wsplit_kernel<<<dim3(DIM_ / 32, KDIM / 32), dim3(32, 8)>>>(wq_w, wqh, wqm, DIM_);
    wsplit_kernel<<<dim3(768  / 32, KDIM / 32), dim3(32, 8)>>>(wkv_w, wkh, wkm, 768);
    wsplit_kernel<<<dim3(DIM_ / 32, KDIM / 32), dim3(32, 8)>>>(proj_w, wph, nullptr, DIM_);

    // q projection (+ fused q-norm) and kv projection: 3-term split-fp16
    hgemm_tma<3><<<dim3(DIM_ / 128, MTOT / 128), 256, 99328>>>(
        mXh, mXm, mWqh, mWqm, wq_b, gq, DIM_, gnq);
    hgemm_tma<3><<<dim3(768 / 128, MTOT / 128), 256, 99328>>>(
        mXh, mXm, mWkh, mWkm, wkv_b, gkvp, 768, nullptr);

    kv_gemm_kernel<<<dim3(B_ * KV_, 8), 256>>>();    // + fused k-norm
    dwc_kernel<<<dim3(32, B_), 384>>>(dwc_w, dwc_b);
    attn_kernel<<<dim3(8, B_ * H_), 256>>>();        // kv reused x4

    // out projection: 1-term fp16 (error not cube-amplified)
    hgemm_tma<1><<<dim3(DIM_ / 128, MTOT / 128), 256, 50176>>>(
        mXh, mXm, mWph, mWph, proj_b, out, DIM_, nullptr);
}

// round 14
// speedup vs baseline: 1.2711x; 1.0392x over previous
#include <cuda_runtime.h>
#include <cuda_fp16.h>
#include <cuda.h>
#include <cstdint>

#define B_   32
#define N_   1024
#define DIM_ 1152
#define H_   12
#define KV_  4
#define D_   96
#define MTOT (B_ * N_)        // 32768
#define KDIM 1152

// ---------------- scratch (device globals; no allocations) ----------------
__device__ float g_q[37748736];            // [B,N,1152] fp32 q
__device__ float g_kvp[25165824];          // [B,N,768] fp32 k|v
__device__ float g_dwc[12582912];          // [B,N,384]
__device__ float g_kv[1179648];            // [B,KV,96,96]
__device__ float g_nq[768];                // (s2,s6) per (b,h)
__device__ float g_nk[256];                // (s2,s6) per (b,kv)
__device__ __align__(128) __half g_xh[37748736];   // A hi  (x, later pre-proj)
__device__ __align__(128) __half g_xm[37748736];   // A mid
__device__ __align__(128) __half g_wqh[1327104];   // wq^T  hi [1152][1152] K-major
__device__ __align__(128) __half g_wqm[1327104];
__device__ __align__(128) __half g_wkh[884736];    // wkv^T hi [768][1152]
__device__ __align__(128) __half g_wkm[884736];
__device__ __align__(128) __half g_wph[1327104];   // proj^T hi

// ---------------- PTX helpers ----------------
__device__ __forceinline__ void mma16(float* c, const uint32_t* a, const uint32_t* b) {
    asm volatile(
        "mma.sync.aligned.m16n8k16.row.col.f32.f16.f16.f32 "
        "{%0,%1,%2,%3},{%4,%5,%6,%7},{%8,%9},{%0,%1,%2,%3};"
        : "+f"(c[0]), "+f"(c[1]), "+f"(c[2]), "+f"(c[3])
        : "r"(a[0]), "r"(a[1]), "r"(a[2]), "r"(a[3]), "r"(b[0]), "r"(b[1]));
}
__device__ __forceinline__ void ldsm4(uint32_t* r, uint32_t addr) {
    asm volatile("ldmatrix.sync.aligned.m8n8.x4.shared.b16 {%0,%1,%2,%3}, [%4];"
        : "=r"(r[0]), "=r"(r[1]), "=r"(r[2]), "=r"(r[3]) : "r"(addr));
}
__device__ __forceinline__ void mbar_init(uint32_t a, uint32_t cnt) {
    asm volatile("mbarrier.init.shared.b64 [%0], %1;" :: "r"(a), "r"(cnt) : "memory");
}
__device__ __forceinline__ void mbar_expect(uint32_t a, uint32_t bytes) {
    asm volatile("mbarrier.arrive.expect_tx.shared.b64 _, [%0], %1;"
                 :: "r"(a), "r"(bytes) : "memory");
}
__device__ __forceinline__ void bar_wait(uint32_t a, uint32_t parity) {
    asm volatile(
        "{\n\t.reg .pred P;\n\t"
        "LAB_%=:\n\t"
        "mbarrier.try_wait.parity.acquire.cta.shared::cta.b64 P, [%0], %1, 0x989680;\n\t"
        "@!P bra LAB_%=;\n\t}"
        :: "r"(a), "r"(parity) : "memory");
}
__device__ __forceinline__ void tma2d(uint32_t dst, const void* map,
                                      int cx, int cy, uint32_t bar) {
    asm volatile(
        "cp.async.bulk.tensor.2d.shared::cta.global.tile.mbarrier::complete_tx::bytes "
        "[%0], [%1, {%2, %3}], [%4];"
        :: "r"(dst), "l"(map), "r"(cx), "r"(cy), "r"(bar) : "memory");
}

#define TILE 8192

// ==== split-fp16 GEMM via TMA + ldmatrix: 128x128 tile, 3-stage pipeline ==
// NT=3: 3-term (~fp32).  NT=1: hi-only.
// qnrm != nullptr (q-proj only): fused focus-norm partials (s2,s6) per (b,h).
template<int NT>
__global__ __launch_bounds__(256, 2) void hgemm_tma(
    const __grid_constant__ CUtensorMap mAh,
    const __grid_constant__ CUtensorMap mAm,
    const __grid_constant__ CUtensorMap mBh,
    const __grid_constant__ CUtensorMap mBm,
    const float* __restrict__ bias, float* __restrict__ C, int Nout,
    float* qnrm)
{
    extern __shared__ __align__(1024) char smem[];
    constexpr int NTILES = (NT == 3) ? 4 : 2;   // Ah[,Am],Bh[,Bm]
    constexpr int STAGE  = NTILES * TILE;
    constexpr int BHOFF  = ((NT == 3) ? 2 : 1) * TILE;
    const uint32_t sb = (uint32_t)__cvta_generic_to_shared(smem);
    const uint32_t bars = sb;                    // 3 mbarriers @ 0,8,16
    const uint32_t tiles_s = sb + 1024;
    float* nbins = (float*)(smem + 64);          // 4 floats, header scratch

    const int tid  = threadIdx.x;
    const int lane = tid & 31, warp = tid >> 5;
    const int wm = warp >> 2, wn = warp & 3;     // 2 x 4 warps, 64x32 each
    const int gid = lane >> 2, tig = lane & 3;
    const int m8  = lane >> 3, low = lane & 7;   // ldmatrix lane decomposition
    const int arow = blockIdx.y * 128;
    const int brow = blockIdx.x * 128;

    // per-lane ldmatrix address invariants (SW64 swizzle)
    uint32_t aOff[4]; int aSw[4];
    #pragma unroll
    for (int ti = 0; ti < 4; ti++) {
        int r = wm * 64 + ti * 16 + ((m8 & 1) << 3) + low;
        aOff[ti] = (uint32_t)(r * 64);
        aSw[ti] = (r >> 1) & 3;
    }
    uint32_t bOff[2]; int bSw[2];
    #pragma unroll
    for (int p = 0; p < 2; p++) {
        int n = wn * 32 + p * 16 + ((m8 >> 1) << 3) + low;
        bOff[p] = (uint32_t)(n * 64);
        bSw[p] = (n >> 1) & 3;
    }
    const int cAm = m8 >> 1;   // chunk add for A matrices
    const int cBm = m8 & 1;    // chunk add for B matrices

    if (tid == 0) { mbar_init(bars, 1); mbar_init(bars + 8, 1); mbar_init(bars + 16, 1); }
    __syncthreads();

    auto issue = [&](int t, int b) {
        const uint32_t bar = bars + b * 8;
        const uint32_t st = tiles_s + b * STAGE;
        mbar_expect(bar, NTILES * TILE);
        const int k0 = t * 32;
        tma2d(st, &mAh, k0, arow, bar);
        if (NT == 3) {
            tma2d(st + TILE, &mAm, k0, arow, bar);
            tma2d(st + 2 * TILE, &mBh, k0, brow, bar);
            tma2d(st + 3 * TILE, &mBm, k0, brow, bar);
        } else {
            tma2d(st + TILE, &mBh, k0, brow, bar);
        }
    };

    float acc[4][4][4];
    #pragma unroll
    for (int i = 0; i < 4; i++)
        #pragma unroll
        for (int j = 0; j < 4; j++)
            #pragma unroll
            for (int r = 0; r < 4; r++) acc[i][j][r] = 0.f;

    const int T = KDIM / 32;                     // 36
    if (tid == 0) { issue(0, 0); issue(1, 1); issue(2, 2); }

    int buf = 0, ph = 0;
    for (int t = 0; t < T; t++) {
        bar_wait(bars + buf * 8, ph);
        const uint32_t st = tiles_s + buf * STAGE;

        #pragma unroll
        for (int ks = 0; ks < 2; ks++) {
            const int cB = ks * 2 + cBm;
            const int cA = ks * 2 + cAm;
            uint32_t bh[4][2], bm[4][2];
            ldsm4(&bh[0][0], st + BHOFF + bOff[0] + (uint32_t)((cB ^ bSw[0]) << 4));
            ldsm4(&bh[2][0], st + BHOFF + bOff[1] + (uint32_t)((cB ^ bSw[1]) << 4));
            if (NT == 3) {
                ldsm4(&bm[0][0], st + 3 * TILE + bOff[0] + (uint32_t)((cB ^ bSw[0]) << 4));
                ldsm4(&bm[2][0], st + 3 * TILE + bOff[1] + (uint32_t)((cB ^ bSw[1]) << 4));
            }
            #pragma unroll
            for (int ti = 0; ti < 4; ti++) {
                uint32_t ah[4], am[4];
                ldsm4(ah, st + aOff[ti] + (uint32_t)((cA ^ aSw[ti]) << 4));
                if (NT == 3)
                    ldsm4(am, st + TILE + aOff[ti] + (uint32_t)((cA ^ aSw[ti]) << 4));
                #pragma unroll
                for (int tj = 0; tj < 4; tj++) {
                    mma16(acc[ti][tj], ah, bh[tj]);
                    if (NT == 3) {
                        mma16(acc[ti][tj], ah, bm[tj]);
                        mma16(acc[ti][tj], am, bh[tj]);
                    }
                }
            }
        }
        __syncthreads();                          // all warps done with buf
        if (t + 3 < T && tid == 0) issue(t + 3, buf);
        buf++; if (buf == 3) { buf = 0; ph ^= 1; }
    }

    float s2l[2] = {0.f, 0.f}, s6l[2] = {0.f, 0.f};
    const int h0 = brow / 96;

    #pragma unroll
    for (int ti = 0; ti < 4; ti++) {
        #pragma unroll
        for (int tj = 0; tj < 4; tj++) {
            int row = arow + wm * 64 + ti * 16 + gid;
            int col = brow + wn * 32 + tj * 8 + tig * 2;
            float b0 = bias[col], b1 = bias[col + 1];
            float2 v0 = { acc[ti][tj][0] + b0, acc[ti][tj][1] + b1 };
            float2 v1 = { acc[ti][tj][2] + b0, acc[ti][tj][3] + b1 };
            *(float2*)(C + (size_t)row * Nout + col) = v0;
            *(float2*)(C + (size_t)(row + 8) * Nout + col) = v1;
            if (NT == 3 && qnrm) {
                int hb = col / 96 - h0;           // 0 or 1 (pair shares head)
                float r0 = fmaxf(v0.x, 0.f), r1 = fmaxf(v0.y, 0.f);
                float r2 = fmaxf(v1.x, 0.f), r3 = fmaxf(v1.y, 0.f);
                float q2 = r0 * r0 + r1 * r1 + r2 * r2 + r3 * r3;
                float c0 = r0 * r0 * r0, c1 = r1 * r1 * r1;
                float c2 = r2 * r2 * r2, c3 = r3 * r3 * r3;
                float q6 = c0 * c0 + c1 * c1 + c2 * c2 + c3 * c3;
                s2l[hb] += q2;
                s6l[hb] += q6;
            }
        }
    }

    if (NT == 3 && qnrm) {
        if (tid < 4) nbins[tid] = 0.f;
        __syncthreads();
        atomicAdd(&nbins[0], s2l[0]);
        atomicAdd(&nbins[1], s6l[0]);
        atomicAdd(&nbins[2], s2l[1]);
        atomicAdd(&nbins[3], s6l[1]);
        __syncthreads();
        if (tid < 4) {
            int head = h0 + (tid >> 1);
            int b = blockIdx.y >> 3;              // arow/1024
            atomicAdd(&qnrm[(b * H_ + head) * 2 + (tid & 1)], nbins[tid]);
        }
    }
}

// ---- split fp32 -> fp16 hi/mid ------------------------------------------
__global__ void split_kernel(const float* __restrict__ src,
                             __half* __restrict__ hi,
                             __half* __restrict__ mid, int n4)
{
    int i = blockIdx.x * blockDim.x + threadIdx.x;
    if (i >= n4) return;
    float4 v = ((const float4*)src)[i];
    __half h0 = __float2half(v.x), h1 = __float2half(v.y);
    __half h2 = __float2half(v.z), h3 = __float2half(v.w);
    __half2* hp = (__half2*)(hi + (size_t)i * 4);
    hp[0] = __half2(h0, h1);
    hp[1] = __half2(h2, h3);
    __half2* mp = (__half2*)(mid + (size_t)i * 4);
    mp[0] = __half2(__float2half(v.x - __half2float(h0)),
                    __float2half(v.y - __half2float(h1)));
    mp[1] = __half2(__float2half(v.z - __half2float(h2)),
                    __float2half(v.w - __half2float(h3)));
}

// ---- weight transpose + split: W[k][n] -> wT_hi/mid[n][k] ----------------
__global__ void wsplit_kernel(const float* __restrict__ W,
                              __half* __restrict__ hi,
                              __half* __restrict__ mid, int Nout)
{
    __shared__ float t[32][33];
    const int k0 = blockIdx.y * 32, nn0 = blockIdx.x * 32;
    const int tx = threadIdx.x, ty = threadIdx.y;
    for (int r = ty; r < 32; r += 8)
        t[r][tx] = W[(size_t)(k0 + r) * Nout + nn0 + tx];
    __syncthreads();
    for (int r = ty; r < 32; r += 8) {
        float v = t[tx][r];   // = W[k0+tx][nn0+r]
        __half h = __float2half(v);
        size_t o = (size_t)(nn0 + r) * KDIM + k0 + tx;
        hi[o] = h;
        if (mid) mid[o] = __float2half(v - __half2float(h));
    }
}

// ---- kv[d,e] += sum_n relu(k)^3 * v ; fused k-norm partials --------------
__global__ __launch_bounds__(256) void kv_gemm_kernel()
{
    const int b = blockIdx.x >> 2;
    const int g = blockIdx.x & 3;
    __shared__ float ks[32 * 96];
    __shared__ float vs[32 * 96];
    const int tid = threadIdx.x;
    const int ty = tid >> 4, tx = tid & 15;

    float acc[6][6];
    #pragma unroll
    for (int i = 0; i < 6; i++)
        #pragma unroll
        for (int j = 0; j < 6; j++) acc[i][j] = 0.f;

    float s2 = 0.f, s6 = 0.f;

    const float* kbase = g_kvp + (size_t)b * N_ * 768 + g * D_;
    const float* vbase = kbase + 384;
    const int t0b = blockIdx.y * 128;

    for (int t0 = t0b; t0 < t0b + 128; t0 += 32) {
        for (int i = tid; i < 32 * 96; i += 256) {
            int r = i / 96;
            int c = i - r * 96;
            size_t off = (size_t)(t0 + r) * 768 + c;
            float kl = fmaxf(kbase[off], 0.f);
            float k3 = kl * kl * kl;
            ks[i] = k3;
            vs[i] = vbase[off];
            s2 += kl * kl;
            s6 += k3 * k3;
        }
        __syncthreads();
        #pragma unroll 8
        for (int kk = 0; kk < 32; kk++) {
            float rk[6], rv[6];
            #pragma unroll
            for (int i = 0; i < 6; i++) rk[i] = ks[kk * 96 + ty * 6 + i];
            #pragma unroll
            for (int j = 0; j < 6; j++) rv[j] = vs[kk * 96 + tx * 6 + j];
            #pragma unroll
            for (int i = 0; i < 6; i++)
                #pragma unroll
                for (int j = 0; j < 6; j++)
                    acc[i][j] = fmaf(rk[i], rv[j], acc[i][j]);
        }
        __syncthreads();
    }
    float* dst = g_kv + (size_t)blockIdx.x * 96 * 96;
    #pragma unroll
    for (int i = 0; i < 6; i++)
        #pragma unroll
        for (int j = 0; j < 6; j++)
            atomicAdd(&dst[(ty * 6 + i) * 96 + tx * 6 + j], acc[i][j]);

    #pragma unroll
    for (int off = 16; off; off >>= 1) {
        s2 += __shfl_xor_sync(0xffffffffu, s2, off);
        s6 += __shfl_xor_sync(0xffffffffu, s6, off);
    }
    __shared__ float w2[8], w6[8];
    const int lane = tid & 31, warp = tid >> 5;
    if (lane == 0) { w2[warp] = s2; w6[warp] = s6; }
    __syncthreads();
    if (tid == 0) {
        float t2 = 0.f, t6 = 0.f;
        #pragma unroll
        for (int i = 0; i < 8; i++) { t2 += w2[i]; t6 += w6[i]; }
        atomicAdd(&g_nk[blockIdx.x * 2], t2);
        atomicAdd(&g_nk[blockIdx.x * 2 + 1], t6);
    }
}

// ---- depthwise 3x3 conv --------------------------------------------------
__global__ __launch_bounds__(384) void dwc_kernel(const float* __restrict__ w,
                                                  const float* __restrict__ bia)
{
    const int y = blockIdx.x;
    const int b = blockIdx.y;
    const int c = threadIdx.x;

    float wr[9];
    #pragma unroll
    for (int i = 0; i < 9; i++) wr[i] = w[c * 9 + i];
    const float bv = bia[c];

    const float* base = g_kvp + (size_t)b * N_ * 768 + 384 + c;
    const float* r0 = base + (size_t)(y * 32) * 768;
    const float* rm = r0 - (size_t)32 * 768;
    const float* rp = r0 + (size_t)32 * 768;
    const bool vm = (y > 0), vp = (y < 31);

    float A0 = 0.f, A1 = 0.f, A2 = 0.f;
    float Bc0, Bc1, Bc2, Cc0, Cc1, Cc2;
    Bc0 = vm ? rm[0] : 0.f;
    Bc1 = r0[0];
    Bc2 = vp ? rp[0] : 0.f;

    float* out = g_dwc + (size_t)(b * N_ + y * 32) * 384 + c;
    for (int x = 0; x < 32; x++) {
        if (x < 31) {
            size_t o = (size_t)(x + 1) * 768;
            Cc0 = vm ? rm[o] : 0.f;
            Cc1 = r0[o];
            Cc2 = vp ? rp[o] : 0.f;
        } else {
            Cc0 = Cc1 = Cc2 = 0.f;
        }
        float o = bv;
        o = fmaf(A0, wr[0], o); o = fmaf(Bc0, wr[1], o); o = fmaf(Cc0, wr[2], o);
        o = fmaf(A1, wr[3], o); o = fmaf(Bc1, wr[4], o); o = fmaf(Cc1, wr[5], o);
        o = fmaf(A2, wr[6], o); o = fmaf(Bc2, wr[7], o); o = fmaf(Cc2, wr[8], o);
        out[(size_t)x * 384] = o;
        A0 = Bc0; A1 = Bc1; A2 = Bc2;
        Bc0 = Cc0; Bc1 = Cc1; Bc2 = Cc2;
    }
}

// ---- attn + scale + dwc add; kv tile reused across 4 q-chunks ------------
__global__ __launch_bounds__(256) void attn_kernel()
{
    __shared__ float kvs[96 * 96];
    __shared__ float qs[32 * 96];
    const int bh = blockIdx.y;
    const int b = bh / H_;
    const int h = bh - b * H_;
    const int g = h & 3;
    const int nbase = blockIdx.x * 128;
    const int tid = threadIdx.x;

    const float* kvsrc = g_kv + (size_t)(b * KV_ + g) * 9216;
    for (int i = tid; i < 9216; i += 256) kvs[i] = kvsrc[i];

    const float s2q = g_nq[bh * 2],            s6q = g_nq[bh * 2 + 1];
    const float s2k = g_nk[(b * KV_ + g) * 2], s6k = g_nk[(b * KV_ + g) * 2 + 1];
    const float den = s6q * s6k;
    const float scale = (den > 0.f) ? sqrtf((s2q * s2k) / den) : 0.f;

    const int ty = tid >> 4, tx = tid & 15;

    for (int c4 = 0; c4 < 4; c4++) {
        const int n0 = nbase + c4 * 32;
        const float* qsrc = g_q + (size_t)(b * N_ + n0) * DIM_ + h * D_;
        for (int i = tid; i < 3072; i += 256) {
            int r = i / 96;
            int d = i - r * 96;
            float v = fmaxf(qsrc[(size_t)r * DIM_ + d], 0.f);
            qs[i] = v * v * v;
        }
        __syncthreads();

        float acc[2][6];
        #pragma unroll
        for (int i = 0; i < 2; i++)
            #pragma unroll
            for (int j = 0; j < 6; j++) acc[i][j] = 0.f;

        #pragma unroll 4
        for (int k = 0; k < 96; k++) {
            float q0 = qs[(ty * 2 + 0) * 96 + k];
            float q1 = qs[(ty * 2 + 1) * 96 + k];
            float rv[6];
            #pragma unroll
            for (int j = 0; j < 6; j++) rv[j] = kvs[k * 96 + tx * 6 + j];
            #pragma unroll
            for (int j = 0; j < 6; j++) {
                acc[0][j] = fmaf(q0, rv[j], acc[0][j]);
                acc[1][j] = fmaf(q1, rv[j], acc[1][j]);
            }
        }

        const float* dsrc = g_dwc + (size_t)(b * N_ + n0) * 384 + g * D_;
        #pragma unroll
        for (int i = 0; i < 2; i++) {
            int r = ty * 2 + i;
            size_t rowbase = (size_t)(b * N_ + n0 + r) * DIM_ + h * D_;
            #pragma unroll
            for (int j = 0; j < 6; j++) {
                int e = tx * 6 + j;
                float val = acc[i][j] * scale + dsrc[(size_t)r * 384 + e];
                g_xh[rowbase + e] = __float2half(val);
            }
        }
        __syncthreads();   // qs reused next chunk
    }
}

// ---------------- host: tensor-map construction ----------------
typedef CUresult (*PFN_tmap)(
    CUtensorMap*, CUtensorMapDataType, cuuint32_t, void*,
    const cuuint64_t*, const cuuint64_t*, const cuuint32_t*, const cuuint32_t*,
    CUtensorMapInterleave, CUtensorMapSwizzle, CUtensorMapL2promotion,
    CUtensorMapFloatOOBfill);

static void make_map(PFN_tmap fn, CUtensorMap* m, void* ptr, uint64_t rows)
{
    cuuint64_t dims[2]    = { (cuuint64_t)KDIM, (cuuint64_t)rows };
    cuuint64_t strides[1] = { (cuuint64_t)KDIM * 2 };
    cuuint32_t box[2]     = { 32, 128 };
    cuuint32_t es[2]      = { 1, 1 };
    fn(m, CU_TENSOR_MAP_DATA_TYPE_FLOAT16, 2, ptr, dims, strides, box, es,
       CU_TENSOR_MAP_INTERLEAVE_NONE, CU_TENSOR_MAP_SWIZZLE_64B,
       CU_TENSOR_MAP_L2_PROMOTION_L2_128B, CU_TENSOR_MAP_FLOAT_OOB_FILL_NONE);
}

// ---------------- launch ----------------
extern "C" void kernel_launch(void* const* d_in, const int* in_sizes, int n_in,
                              void* d_out, int out_size)
{
    const float* x      = (const float*)d_in[0];
    const float* wq_w   = (const float*)d_in[1];
    const float* wq_b   = (const float*)d_in[2];
    const float* wkv_w  = (const float*)d_in[3];
    const float* wkv_b  = (const float*)d_in[4];
    const float* dwc_w  = (const float*)d_in[5];
    const float* dwc_b  = (const float*)d_in[6];
    const float* proj_w = (const float*)d_in[7];
    const float* proj_b = (const float*)d_in[8];
    float* out = (float*)d_out;

    cudaFuncSetAttribute(hgemm_tma<3>, cudaFuncAttributeMaxDynamicSharedMemorySize, 99328);
    cudaFuncSetAttribute(hgemm_tma<1>, cudaFuncAttributeMaxDynamicSharedMemorySize, 50176);

    float *gq, *gkvp, *gnq, *gnk, *gkv;
    __half *xh, *xm, *wqh, *wqm, *wkh, *wkm, *wph;
    cudaGetSymbolAddress((void**)&gq,   g_q);
    cudaGetSymbolAddress((void**)&gkvp, g_kvp);
    cudaGetSymbolAddress((void**)&gnq,  g_nq);
    cudaGetSymbolAddress((void**)&gnk,  g_nk);
    cudaGetSymbolAddress((void**)&gkv,  g_kv);
    cudaGetSymbolAddress((void**)&xh,   g_xh);
    cudaGetSymbolAddress((void**)&xm,   g_xm);
    cudaGetSymbolAddress((void**)&wqh,  g_wqh);
    cudaGetSymbolAddress((void**)&wqm,  g_wqm);
    cudaGetSymbolAddress((void**)&wkh,  g_wkh);
    cudaGetSymbolAddress((void**)&wkm,  g_wkm);
    cudaGetSymbolAddress((void**)&wph,  g_wph);

    static PFN_tmap fn = nullptr;
    static cudaStream_t s1 = nullptr;
    static cudaEvent_t eStart = nullptr, eW = nullptr, eKV = nullptr, eAux = nullptr;
    if (!fn) {
        cudaDriverEntryPointQueryResult qr;
        cudaGetDriverEntryPoint("cuTensorMapEncodeTiled", (void**)&fn,
                                cudaEnableDefault, &qr);
        cudaStreamCreateWithFlags(&s1, cudaStreamNonBlocking);
        cudaEventCreateWithFlags(&eStart, cudaEventDisableTiming);
        cudaEventCreateWithFlags(&eW,     cudaEventDisableTiming);
        cudaEventCreateWithFlags(&eKV,    cudaEventDisableTiming);
        cudaEventCreateWithFlags(&eAux,   cudaEventDisableTiming);
    }
    CUtensorMap mXh, mXm, mWqh, mWqm, mWkh, mWkm, mWph;
    make_map(fn, &mXh,  xh,  MTOT);
    make_map(fn, &mXm,  xm,  MTOT);
    make_map(fn, &mWqh, wqh, DIM_);
    make_map(fn, &mWqm, wqm, DIM_);
    make_map(fn, &mWkh, wkh, 768);
    make_map(fn, &mWkm, wkm, 768);
    make_map(fn, &mWph, wph, DIM_);

    cudaMemsetAsync(gnq, 0, 768 * sizeof(float));
    cudaMemsetAsync(gnk, 0, 256 * sizeof(float));
    cudaMemsetAsync(gkv, 0, 1179648 * sizeof(float));

    // fork side stream
    cudaEventRecord(eStart, 0);
    cudaStreamWaitEvent(s1, eStart, 0);

    // side stream: wq/proj weight splits (independent of x split)
    wsplit_kernel<<<dim3(DIM_ / 32, KDIM / 32), dim3(32, 8), 0, s1>>>(wq_w, wqh, wqm, DIM_);
    wsplit_kernel<<<dim3(DIM_ / 32, KDIM / 32), dim3(32, 8), 0, s1>>>(proj_w, wph, nullptr, DIM_);
    cudaEventRecord(eW, s1);

    // main stream: x split + wkv split, then kv projection
    split_kernel<<<(MTOT * DIM_ / 4 + 255) / 256, 256>>>(x, xh, xm, MTOT * DIM_ / 4);
    wsplit_kernel<<<dim3(768 / 32, KDIM / 32), dim3(32, 8)>>>(wkv_w, wkh, wkm, 768);
    hgemm_tma<3><<<dim3(768 / 128, MTOT / 128), 256, 99328>>>(
        mXh, mXm, mWkh, mWkm, wkv_b, gkvp, 768, nullptr);
    cudaEventRecord(eKV, 0);

    // side stream: kv_gemm (+k-norm) and dwc in the shadow of the q GEMM
    cudaStreamWaitEvent(s1, eKV, 0);
    kv_gemm_kernel<<<dim3(B_ * KV_, 8), 256, 0, s1>>>();
    dwc_kernel<<<dim3(32, B_), 384, 0, s1>>>(dwc_w, dwc_b);
    cudaEventRecord(eAux, s1);

    // main stream: q projection (+ fused q-norm)
    cudaStreamWaitEvent(0, eW, 0);
    hgemm_tma<3><<<dim3(DIM_ / 128, MTOT / 128), 256, 99328>>>(
        mXh, mXm, mWqh, mWqm, wq_b, gq, DIM_, gnq);

    // join, then attn and final projection
    cudaStreamWaitEvent(0, eAux, 0);
    attn_kernel<<<dim3(8, B_ * H_), 256>>>();
    hgemm_tma<1><<<dim3(DIM_ / 128, MTOT / 128), 256, 50176>>>(
        mXh, mXm, mWph, mWph, proj_b, out, DIM_, nullptr);
}